// round 13
// baseline (speedup 1.0000x reference)
#include <cuda_runtime.h>
#include <cuda_bf16.h>
#include <cstdint>

#define NNODES 40000
#define NEDGES 640000
#define HID    128
#define MROWS  80000   // BATCH * NNODES
#define KPAD   40      // padded k-stride (bf16 elems) -> 80B rows, ldmatrix conflict-free
#define NBLK   157     // ceil(40000/256) scan blocks

// ---------------- device scratch (no allocations allowed) ----------------
__device__ float g_X[(size_t)MROWS * HID];
__device__ float g_NET[(size_t)MROWS * HID];
__device__ float g_AGG[(size_t)MROWS * HID];   // only used as Yf scratch in final layer
__device__ short g_Q[(size_t)MROWS * HID];     // int16 relu(x) (spmm input)
__device__ short g_AGGQ[(size_t)MROWS * HID];  // int16 spmm output
__device__ float g_AS[MROWS];                  // AGG dequant scale per row
__device__ float2 g_S2[NNODES];                // Q dequant scale {batch0, batch1}
__device__ int   g_rowptr[NNODES + 1];
__device__ int   g_cursor[NNODES];
__device__ int   g_cols[NEDGES];
__device__ float g_vals[NEDGES];
__device__ int   g_scanbuf[NBLK * 256];
__device__ int   g_bsum[NBLK];
// pre-split transposed weights: [4 layers][8 chunks][n=128][k=KPAD] bf16 hi/lo
__device__ unsigned short g_Bh16[4 * 8 * 128 * KPAD];
__device__ unsigned short g_Bl16[4 * 8 * 128 * KPAD];

// ---------------- helpers ----------------
__device__ __forceinline__ uint32_t smem_u32(const void* p) {
    uint32_t a;
    asm("{ .reg .u64 t; cvta.to.shared.u64 t, %1; cvt.u32.u64 %0, t; }" : "=r"(a) : "l"(p));
    return a;
}

__device__ __forceinline__ void split_bf16(float v, unsigned short& hi, unsigned short& lo) {
    __nv_bfloat16 h = __float2bfloat16(v);
    float r = v - __bfloat162float(h);
    __nv_bfloat16 l = __float2bfloat16(r);
    hi = __bfloat16_as_ushort(h);
    lo = __bfloat16_as_ushort(l);
}

#define LDSM4(r0, r1, r2, r3, addr) \
    asm volatile("ldmatrix.sync.aligned.m8n8.x4.shared.b16 {%0,%1,%2,%3}, [%4];" \
        : "=r"(r0), "=r"(r1), "=r"(r2), "=r"(r3) : "r"(addr))

#define MMA16816(d, a, b0, b1) \
    asm volatile("mma.sync.aligned.m16n8k16.row.col.f32.bf16.bf16.f32 " \
        "{%0,%1,%2,%3}, {%4,%5,%6,%7}, {%8,%9}, {%0,%1,%2,%3};" \
        : "+f"((d)[0]), "+f"((d)[1]), "+f"((d)[2]), "+f"((d)[3]) \
        : "r"((a)[0]), "r"((a)[1]), "r"((a)[2]), "r"((a)[3]), "r"(b0), "r"(b1))

#define CP16(dst, src) \
    asm volatile("cp.async.cg.shared.global [%0], [%1], 16;" :: "r"(dst), "l"(src))
#define CP_COMMIT() asm volatile("cp.async.commit_group;" ::: "memory")
#define CP_WAIT0()  asm volatile("cp.async.wait_group 0;" ::: "memory")

// ---------------- front kernel: zero ∥ weight prep ∥ init linear (+quant) ----------------
#define PREP_BLKS 128            // 32768 threads
#define ZERO_BLKS NBLK           // 157
#define INIT_BLKS 10000          // MROWS*32/256

__global__ void k_front(const float* __restrict__ p, const float* __restrict__ Wi,
                        const float* __restrict__ bi,
                        const float* __restrict__ Ws_b, const float* __restrict__ Wf_b) {
    int b = blockIdx.x;
    int tid = threadIdx.x;
    if (b < PREP_BLKS) {
        int idx = b * 256 + tid;             // (L, c, n, kq)
        int kq = idx & 7;
        int n = (idx >> 3) & 127;
        int c = (idx >> 10) & 7;
        int L = idx >> 13;
        const float* Ws = Ws_b + (size_t)L * HID * HID;
        const float* Wf = Wf_b + (size_t)L * HID * HID;
        size_t base = ((size_t)(L * 8 + c) * 128 + n) * KPAD;
        #pragma unroll
        for (int e = 0; e < 4; ++e) {
            int k = kq * 4 + e;
            int gk = c * 32 + k;
            float v = (gk < HID) ? Ws[(size_t)gk * HID + n] : Wf[(size_t)(gk - HID) * HID + n];
            unsigned short hi, lo;
            split_bf16(v, hi, lo);
            g_Bh16[base + k] = hi;
            g_Bl16[base + k] = lo;
        }
        return;
    }
    if (b < PREP_BLKS + ZERO_BLKS) {
        int i = (b - PREP_BLKS) * 256 + tid;
        if (i < NNODES) g_cursor[i] = 0;
        return;
    }
    // init: x = p @ W_init + b_init, warp per row; fused int16 quant of relu(x)
    int idx = (b - PREP_BLKS - ZERO_BLKS) * 256 + tid;
    int m = idx >> 5;
    int lane = idx & 31;
    int h = lane * 4;
    float p0 = p[m * 3 + 0], p1 = p[m * 3 + 1], p2 = p[m * 3 + 2];
    float4 w0 = *(const float4*)&Wi[0 * HID + h];
    float4 w1 = *(const float4*)&Wi[1 * HID + h];
    float4 w2 = *(const float4*)&Wi[2 * HID + h];
    float4 bb = *(const float4*)&bi[h];
    float4 o;
    o.x = fmaf(p0, w0.x, fmaf(p1, w1.x, fmaf(p2, w2.x, bb.x)));
    o.y = fmaf(p0, w0.y, fmaf(p1, w1.y, fmaf(p2, w2.y, bb.y)));
    o.z = fmaf(p0, w0.z, fmaf(p1, w1.z, fmaf(p2, w2.z, bb.z)));
    o.w = fmaf(p0, w0.w, fmaf(p1, w1.w, fmaf(p2, w2.w, bb.w)));
    *(float4*)&g_X[(size_t)m * HID + h] = o;
    float rx = fmaxf(o.x, 0.f), ry = fmaxf(o.y, 0.f);
    float rz = fmaxf(o.z, 0.f), rw = fmaxf(o.w, 0.f);
    float mx = fmaxf(fmaxf(rx, ry), fmaxf(rz, rw));
    #pragma unroll
    for (int of = 16; of; of >>= 1)
        mx = fmaxf(mx, __shfl_xor_sync(0xffffffffu, mx, of));
    float inv = (mx > 0.f) ? 32766.f / mx : 0.f;
    short4 q;
    q.x = (short)__float2int_rn(rx * inv);
    q.y = (short)__float2int_rn(ry * inv);
    q.z = (short)__float2int_rn(rz * inv);
    q.w = (short)__float2int_rn(rw * inv);
    *(short4*)&g_Q[(size_t)m * HID + h] = q;
    if (lane == 0) {
        float sc = (mx > 0.f) ? mx * (1.f / 32766.f) : 0.f;
        if (m < NNODES) g_S2[m].x = sc;
        else            g_S2[m - NNODES].y = sc;
    }
}

// ---------------- CSR build (proven 3-phase scan) ----------------
__global__ void k_hist(const int* __restrict__ rows) {
    int i = blockIdx.x * blockDim.x + threadIdx.x;
    if (i < NEDGES) atomicAdd(&g_cursor[rows[i]], 1);
}

__global__ void k_scanA() {
    __shared__ int ws[8];
    int tid = threadIdx.x, lane = tid & 31, wid = tid >> 5;
    int i = blockIdx.x * 256 + tid;
    int c = (i < NNODES) ? g_cursor[i] : 0;
    int v = c;
    #pragma unroll
    for (int o = 1; o < 32; o <<= 1) {
        int t = __shfl_up_sync(0xffffffffu, v, o);
        if (lane >= o) v += t;
    }
    if (lane == 31) ws[wid] = v;
    __syncthreads();
    if (wid == 0) {
        int w = (lane < 8) ? ws[lane] : 0;
        #pragma unroll
        for (int o = 1; o < 8; o <<= 1) {
            int t = __shfl_up_sync(0xffffffffu, w, o);
            if (lane >= o) w += t;
        }
        if (lane < 8) ws[lane] = w;
    }
    __syncthreads();
    int incl = v + (wid > 0 ? ws[wid - 1] : 0);
    g_scanbuf[blockIdx.x * 256 + tid] = incl;
    if (tid == 255) g_bsum[blockIdx.x] = incl;
}

__global__ void k_scanB() {
    __shared__ int ws[8];
    int tid = threadIdx.x, lane = tid & 31, wid = tid >> 5;
    int b = (tid < NBLK) ? g_bsum[tid] : 0;
    int v = b;
    #pragma unroll
    for (int o = 1; o < 32; o <<= 1) {
        int t = __shfl_up_sync(0xffffffffu, v, o);
        if (lane >= o) v += t;
    }
    if (lane == 31) ws[wid] = v;
    __syncthreads();
    if (wid == 0) {
        int w = (lane < 8) ? ws[lane] : 0;
        #pragma unroll
        for (int o = 1; o < 8; o <<= 1) {
            int t = __shfl_up_sync(0xffffffffu, w, o);
            if (lane >= o) w += t;
        }
        if (lane < 8) ws[lane] = w;
    }
    __syncthreads();
    int incl = v + (wid > 0 ? ws[wid - 1] : 0);
    if (tid < NBLK) g_bsum[tid] = incl - b;   // exclusive
}

__global__ void k_scanC() {
    int i = blockIdx.x * 256 + threadIdx.x;
    if (i < NNODES) {
        int incl = g_scanbuf[blockIdx.x * 256 + threadIdx.x] + g_bsum[blockIdx.x];
        int c = g_cursor[i];
        g_rowptr[i + 1] = incl;
        g_cursor[i] = incl - c;
        if (i == 0) g_rowptr[0] = 0;
    }
}

__global__ void k_scatter(const int* __restrict__ rows, const int* __restrict__ cols,
                          const float* __restrict__ vals) {
    int i = blockIdx.x * blockDim.x + threadIdx.x;
    if (i < NEDGES) {
        int r = rows[i];
        int pos = atomicAdd(&g_cursor[r], 1);
        g_cols[pos] = cols[i];
        g_vals[pos] = vals[i];
    }
}

// ---------------- spmm: AGGQ = quant(A * dequant(Q)), warp = node, half-warp = batch ----------------
__device__ __forceinline__ void acc8(float* acc, int4 r, float vs) {
    acc[0] = fmaf(vs, (float)(short)(r.x), acc[0]);
    acc[1] = fmaf(vs, (float)(short)(r.x >> 16), acc[1]);
    acc[2] = fmaf(vs, (float)(short)(r.y), acc[2]);
    acc[3] = fmaf(vs, (float)(short)(r.y >> 16), acc[3]);
    acc[4] = fmaf(vs, (float)(short)(r.z), acc[4]);
    acc[5] = fmaf(vs, (float)(short)(r.z >> 16), acc[5]);
    acc[6] = fmaf(vs, (float)(short)(r.w), acc[6]);
    acc[7] = fmaf(vs, (float)(short)(r.w >> 16), acc[7]);
}

__global__ void k_spmm() {
    int w = (blockIdx.x * blockDim.x + threadIdx.x) >> 5;   // node
    int lane = threadIdx.x & 31;
    if (w >= NNODES) return;
    int half = lane >> 4, li = lane & 15;
    const short* __restrict__ qbase = g_Q + (size_t)half * NNODES * HID;
    int s = g_rowptr[w], e = g_rowptr[w + 1];
    float acc[8];
    #pragma unroll
    for (int k = 0; k < 8; ++k) acc[k] = 0.f;
    int j = s;
    for (; j + 2 <= e; j += 2) {
        int c0 = g_cols[j], c1 = g_cols[j + 1];
        float v0 = g_vals[j], v1 = g_vals[j + 1];
        float2 sA = g_S2[c0], sB = g_S2[c1];
        int4 r0 = *(const int4*)(qbase + (size_t)c0 * HID + li * 8);
        int4 r1 = *(const int4*)(qbase + (size_t)c1 * HID + li * 8);
        acc8(acc, r0, v0 * (half ? sA.y : sA.x));
        acc8(acc, r1, v1 * (half ? sB.y : sB.x));
    }
    if (j < e) {
        int c0 = g_cols[j];
        float v0 = g_vals[j];
        float2 sA = g_S2[c0];
        int4 r0 = *(const int4*)(qbase + (size_t)c0 * HID + li * 8);
        acc8(acc, r0, v0 * (half ? sA.y : sA.x));
    }
    // quantize row (abs-max within 16-lane group)
    float m = 0.f;
    #pragma unroll
    for (int k = 0; k < 8; ++k) m = fmaxf(m, fabsf(acc[k]));
    #pragma unroll
    for (int o = 8; o; o >>= 1)
        m = fmaxf(m, __shfl_xor_sync(0xffffffffu, m, o));
    float inv = (m > 0.f) ? 32766.f / m : 0.f;
    int q[8];
    #pragma unroll
    for (int k = 0; k < 8; ++k) q[k] = __float2int_rn(acc[k] * inv);
    int4 packed;
    packed.x = (q[0] & 0xffff) | (q[1] << 16);
    packed.y = (q[2] & 0xffff) | (q[3] << 16);
    packed.z = (q[4] & 0xffff) | (q[5] << 16);
    packed.w = (q[6] & 0xffff) | (q[7] << 16);
    *(int4*)&g_AGGQ[((size_t)half * NNODES + w) * HID + li * 8] = packed;
    if (li == 0) g_AS[half * NNODES + w] = (m > 0.f) ? m * (1.f / 32766.f) : 0.f;
}

// ---------------- mma.sync bf16 3-split GEMM, double-buffered + fused output quant ----------------
#define CHUNK_BYTES (128 * KPAD * 2)
#define BUF_BYTES   (4 * CHUNK_BYTES)
#define SMEM_DYN_GEMM (2 * BUF_BYTES)

__global__ void __launch_bounds__(512, 1) k_gemm_mma(int mode, int L, int doq,
        const float* __restrict__ bs, const float* __restrict__ bf) {
    const float* __restrict__ A1 = mode ? g_NET : g_X;
    float* __restrict__ C = mode ? g_X : g_NET;

    extern __shared__ __align__(16) char dyn_smem[];
    __shared__ float s_bias[128];
    __shared__ float s_rmax[4][128];

    const int tid = threadIdx.x;
    const int lane = tid & 31, w = tid >> 5;
    const int m0 = blockIdx.x * 128;
    const int mw = (w & 3) * 32;
    const int nw = (w >> 2) * 32;

    if (tid < 128) s_bias[tid] = bs[tid] + bf[tid];

    const uint32_t sb = smem_u32(dyn_smem);

    const int a_row = lane & 15;
    const int a_k   = (lane >> 4) * 8;
    const int b_row = ((lane >> 4) & 1) * 8 + (lane & 7);
    const int b_k   = ((lane >> 3) & 1) * 8;

    float acc[2][4][4];
    #pragma unroll
    for (int i = 0; i < 2; ++i)
        #pragma unroll
        for (int j = 0; j < 4; ++j)
            #pragma unroll
            for (int q = 0; q < 4; ++q) acc[i][j][q] = 0.f;

    const unsigned short* __restrict__ Bh = g_Bh16 + (size_t)L * 8 * 128 * KPAD;
    const unsigned short* __restrict__ Bl = g_Bl16 + (size_t)L * 8 * 128 * KPAD;

    const int row0 = tid >> 3, row1 = (tid + 512) >> 3;
    const int q0 = (tid & 7) * 4, q1 = ((tid + 512) & 7) * 4;

    {
        #pragma unroll
        for (int h = 0; h < 2; ++h) {
            int row = h ? row1 : row0;
            int q = h ? q1 : q0;
            float4 v = *(const float4*)&A1[(size_t)(m0 + row) * HID + q];
            v.x = fmaxf(v.x, 0.f); v.y = fmaxf(v.y, 0.f);
            v.z = fmaxf(v.z, 0.f); v.w = fmaxf(v.w, 0.f);
            unsigned short hh[4], ll[4];
            split_bf16(v.x, hh[0], ll[0]); split_bf16(v.y, hh[1], ll[1]);
            split_bf16(v.z, hh[2], ll[2]); split_bf16(v.w, hh[3], ll[3]);
            uint32_t eo = (uint32_t)(row * KPAD + q) * 2;
            *(uint2*)(dyn_smem + eo) = *(uint2*)hh;
            *(uint2*)(dyn_smem + CHUNK_BYTES + eo) = *(uint2*)ll;
        }
        const char* bh_src = (const char*)Bh;
        const char* bl_src = (const char*)Bl;
        for (int i = tid; i < 640; i += 512) {
            CP16(sb + 2 * CHUNK_BYTES + i * 16, bh_src + i * 16);
            CP16(sb + 3 * CHUNK_BYTES + i * 16, bl_src + i * 16);
        }
        CP_COMMIT();
        CP_WAIT0();
    }
    __syncthreads();

    int buf = 0;
    #pragma unroll 1
    for (int c = 0; c < 8; ++c) {
        float4 vn0, vn1;
        if (c < 7) {
            const int kbase = ((c + 1) & 3) * 32;
            if (c + 1 < 4) {
                vn0 = *(const float4*)&A1[(size_t)(m0 + row0) * HID + kbase + q0];
                vn1 = *(const float4*)&A1[(size_t)(m0 + row1) * HID + kbase + q1];
            } else {
                uint2 a0 = *(const uint2*)&g_AGGQ[(size_t)(m0 + row0) * HID + kbase + q0];
                uint2 a1 = *(const uint2*)&g_AGGQ[(size_t)(m0 + row1) * HID + kbase + q1];
                float sc0 = g_AS[m0 + row0];
                float sc1 = g_AS[m0 + row1];
                vn0 = make_float4(sc0 * (float)(short)(a0.x), sc0 * (float)(short)(a0.x >> 16),
                                  sc0 * (float)(short)(a0.y), sc0 * (float)(short)(a0.y >> 16));
                vn1 = make_float4(sc1 * (float)(short)(a1.x), sc1 * (float)(short)(a1.x >> 16),
                                  sc1 * (float)(short)(a1.y), sc1 * (float)(short)(a1.y >> 16));
            }
            const uint32_t nb = sb + (buf ^ 1) * BUF_BYTES;
            const char* bh_src = (const char*)(Bh + (size_t)(c + 1) * 128 * KPAD);
            const char* bl_src = (const char*)(Bl + (size_t)(c + 1) * 128 * KPAD);
            for (int i = tid; i < 640; i += 512) {
                CP16(nb + 2 * CHUNK_BYTES + i * 16, bh_src + i * 16);
                CP16(nb + 3 * CHUNK_BYTES + i * 16, bl_src + i * 16);
            }
            CP_COMMIT();
        }

        const uint32_t cb = sb + buf * BUF_BYTES;
        #pragma unroll
        for (int ks = 0; ks < 32; ks += 16) {
            uint32_t ah[2][4], al[2][4];
            #pragma unroll
            for (int mt = 0; mt < 2; ++mt) {
                uint32_t ao = (uint32_t)(((mw + mt * 16 + a_row) * KPAD + ks + a_k) * 2);
                LDSM4(ah[mt][0], ah[mt][1], ah[mt][2], ah[mt][3], cb + ao);
                LDSM4(al[mt][0], al[mt][1], al[mt][2], al[mt][3], cb + CHUNK_BYTES + ao);
            }
            #pragma unroll
            for (int nt = 0; nt < 2; ++nt) {
                uint32_t bo = (uint32_t)(((nw + nt * 16 + b_row) * KPAD + ks + b_k) * 2);
                uint32_t bh4[4], bl4[4];
                LDSM4(bh4[0], bh4[1], bh4[2], bh4[3], cb + 2 * CHUNK_BYTES + bo);
                LDSM4(bl4[0], bl4[1], bl4[2], bl4[3], cb + 3 * CHUNK_BYTES + bo);
                #pragma unroll
                for (int mt = 0; mt < 2; ++mt) {
                    #pragma unroll
                    for (int s = 0; s < 2; ++s) {
                        float* d = acc[mt][nt * 2 + s];
                        MMA16816(d, ah[mt], bh4[2 * s], bh4[2 * s + 1]);
                        MMA16816(d, ah[mt], bl4[2 * s], bl4[2 * s + 1]);
                        MMA16816(d, al[mt], bh4[2 * s], bh4[2 * s + 1]);
                    }
                }
            }
        }

        if (c < 7) {
            char* nbp = dyn_smem + (buf ^ 1) * BUF_BYTES;
            if (c + 1 < 4) {
                vn0.x = fmaxf(vn0.x, 0.f); vn0.y = fmaxf(vn0.y, 0.f);
                vn0.z = fmaxf(vn0.z, 0.f); vn0.w = fmaxf(vn0.w, 0.f);
                vn1.x = fmaxf(vn1.x, 0.f); vn1.y = fmaxf(vn1.y, 0.f);
                vn1.z = fmaxf(vn1.z, 0.f); vn1.w = fmaxf(vn1.w, 0.f);
            }
            unsigned short h0[4], l0[4], h1[4], l1[4];
            split_bf16(vn0.x, h0[0], l0[0]); split_bf16(vn0.y, h0[1], l0[1]);
            split_bf16(vn0.z, h0[2], l0[2]); split_bf16(vn0.w, h0[3], l0[3]);
            split_bf16(vn1.x, h1[0], l1[0]); split_bf16(vn1.y, h1[1], l1[1]);
            split_bf16(vn1.z, h1[2], l1[2]); split_bf16(vn1.w, h1[3], l1[3]);
            uint32_t eo0 = (uint32_t)(row0 * KPAD + q0) * 2;
            uint32_t eo1 = (uint32_t)(row1 * KPAD + q1) * 2;
            *(uint2*)(nbp + eo0) = *(uint2*)h0;
            *(uint2*)(nbp + CHUNK_BYTES + eo0) = *(uint2*)l0;
            *(uint2*)(nbp + eo1) = *(uint2*)h1;
            *(uint2*)(nbp + CHUNK_BYTES + eo1) = *(uint2*)l1;
            CP_WAIT0();
            __syncthreads();
            buf ^= 1;
        }
    }

    // ---- epilogue: bias + optional residual -> store C ----
    const int gid = lane >> 2, tig = lane & 3;
    #pragma unroll
    for (int mt = 0; mt < 2; ++mt) {
        #pragma unroll
        for (int nt = 0; nt < 4; ++nt) {
            int m = m0 + mw + mt * 16 + gid;
            int n = nw + nt * 8 + tig * 2;
            float b0 = s_bias[n], b1 = s_bias[n + 1];
            acc[mt][nt][0] += b0; acc[mt][nt][1] += b1;
            acc[mt][nt][2] += b0; acc[mt][nt][3] += b1;
            if (mode) {
                float2 r0 = *(const float2*)&C[(size_t)m * HID + n];
                float2 r1 = *(const float2*)&C[(size_t)(m + 8) * HID + n];
                acc[mt][nt][0] += r0.x; acc[mt][nt][1] += r0.y;
                acc[mt][nt][2] += r1.x; acc[mt][nt][3] += r1.y;
            }
            *(float2*)&C[(size_t)m * HID + n] = make_float2(acc[mt][nt][0], acc[mt][nt][1]);
            *(float2*)&C[(size_t)(m + 8) * HID + n] = make_float2(acc[mt][nt][2], acc[mt][nt][3]);
        }
    }

    // ---- fused quantization of relu(C) for next layer's spmm ----
    if (doq) {
        float rmax[2][2];
        #pragma unroll
        for (int mt = 0; mt < 2; ++mt) {
            float mA = 0.f, mB = 0.f;
            #pragma unroll
            for (int nt = 0; nt < 4; ++nt) {
                mA = fmaxf(mA, fmaxf(acc[mt][nt][0], acc[mt][nt][1]));
                mB = fmaxf(mB, fmaxf(acc[mt][nt][2], acc[mt][nt][3]));
            }
            rmax[mt][0] = mA; rmax[mt][1] = mB;
        }
        #pragma unroll
        for (int mt = 0; mt < 2; ++mt)
            #pragma unroll
            for (int hf = 0; hf < 2; ++hf) {
                float v = rmax[mt][hf];
                v = fmaxf(v, __shfl_xor_sync(0xffffffffu, v, 1));
                v = fmaxf(v, __shfl_xor_sync(0xffffffffu, v, 2));
                rmax[mt][hf] = v;
            }
        const int wg = w >> 2;
        if (tig == 0) {
            #pragma unroll
            for (int mt = 0; mt < 2; ++mt)
                #pragma unroll
                for (int hf = 0; hf < 2; ++hf)
                    s_rmax[wg][mw + mt * 16 + hf * 8 + gid] = rmax[mt][hf];
        }
        __syncthreads();
        #pragma unroll
        for (int mt = 0; mt < 2; ++mt) {
            #pragma unroll
            for (int hf = 0; hf < 2; ++hf) {
                int row = mw + mt * 16 + hf * 8 + gid;
                float rm = fmaxf(fmaxf(s_rmax[0][row], s_rmax[1][row]),
                                 fmaxf(s_rmax[2][row], s_rmax[3][row]));
                float inv = (rm > 0.f) ? 32766.f / rm : 0.f;
                int m = m0 + row;
                #pragma unroll
                for (int nt = 0; nt < 4; ++nt) {
                    int n = nw + nt * 8 + tig * 2;
                    short2 qq;
                    qq.x = (short)__float2int_rn(fmaxf(acc[mt][nt][hf * 2 + 0], 0.f) * inv);
                    qq.y = (short)__float2int_rn(fmaxf(acc[mt][nt][hf * 2 + 1], 0.f) * inv);
                    *(short2*)&g_Q[(size_t)m * HID + n] = qq;
                }
                if (wg == 0 && tig == 0) {
                    float sc = (rm > 0.f) ? rm * (1.f / 32766.f) : 0.f;
                    if (m < NNODES) g_S2[m].x = sc;
                    else            g_S2[m - NNODES].y = sc;
                }
            }
        }
    }
}

// ---------------- final layer: Ys/Yf = relu(x) @ [Ws_out|Wf_out] ----------------
__global__ void k_fin_gemm(const float* __restrict__ Wso, const float* __restrict__ bso,
                           const float* __restrict__ Wfo, const float* __restrict__ bfo,
                           float* __restrict__ out) {
    int w = (blockIdx.x * blockDim.x + threadIdx.x) >> 5;
    int lane = threadIdx.x & 31;
    if (w >= MROWS) return;
    int k0 = lane * 4;
    float4 x = *(const float4*)&g_X[(size_t)w * HID + k0];
    float xv[4] = { fmaxf(x.x, 0.f), fmaxf(x.y, 0.f), fmaxf(x.z, 0.f), fmaxf(x.w, 0.f) };
    float s[6] = {0.f, 0.f, 0.f, 0.f, 0.f, 0.f};
    #pragma unroll
    for (int i = 0; i < 4; ++i) {
        int k = k0 + i;
        s[0] = fmaf(xv[i], Wso[k * 3 + 0], s[0]);
        s[1] = fmaf(xv[i], Wso[k * 3 + 1], s[1]);
        s[2] = fmaf(xv[i], Wso[k * 3 + 2], s[2]);
        s[3] = fmaf(xv[i], Wfo[k * 3 + 0], s[3]);
        s[4] = fmaf(xv[i], Wfo[k * 3 + 1], s[4]);
        s[5] = fmaf(xv[i], Wfo[k * 3 + 2], s[5]);
    }
    #pragma unroll
    for (int o = 16; o; o >>= 1) {
        #pragma unroll
        for (int c = 0; c < 6; ++c)
            s[c] += __shfl_down_sync(0xffffffffu, s[c], o);
    }
    if (lane == 0) {
        out[(size_t)w * 3 + 0] = s[0] + bso[0] + bfo[0];
        out[(size_t)w * 3 + 1] = s[1] + bso[1] + bfo[1];
        out[(size_t)w * 3 + 2] = s[2] + bso[2] + bfo[2];
        g_AGG[(size_t)w * 3 + 0] = s[3];
        g_AGG[(size_t)w * 3 + 1] = s[4];
        g_AGG[(size_t)w * 3 + 2] = s[5];
    }
}

__global__ void k_fin_spmm(float* __restrict__ out) {
    int n = blockIdx.x * blockDim.x + threadIdx.x;
    if (n >= NNODES) return;
    int s = g_rowptr[n], e = g_rowptr[n + 1];
    float a[6] = {0.f, 0.f, 0.f, 0.f, 0.f, 0.f};
    for (int j = s; j < e; ++j) {
        int c = g_cols[j];
        float v = g_vals[j];
        const float* y0 = &g_AGG[(size_t)c * 3];
        const float* y1 = &g_AGG[((size_t)NNODES + c) * 3];
        a[0] = fmaf(v, y0[0], a[0]);
        a[1] = fmaf(v, y0[1], a[1]);
        a[2] = fmaf(v, y0[2], a[2]);
        a[3] = fmaf(v, y1[0], a[3]);
        a[4] = fmaf(v, y1[1], a[4]);
        a[5] = fmaf(v, y1[2], a[5]);
    }
    float* o0 = &out[(size_t)n * 3];
    float* o1 = &out[((size_t)NNODES + n) * 3];
    o0[0] += a[0]; o0[1] += a[1]; o0[2] += a[2];
    o1[0] += a[3]; o1[1] += a[4]; o1[2] += a[5];
}

// ---------------- launch ----------------
extern "C" void kernel_launch(void* const* d_in, const int* in_sizes, int n_in,
                              void* d_out, int out_size) {
    const float* p        = (const float*)d_in[0];
    const float* adj_vals = (const float*)d_in[1];
    const int*   e_rows   = (const int*)d_in[2];
    const int*   e_cols   = (const int*)d_in[3];
    const float* W_init   = (const float*)d_in[4];
    const float* b_init   = (const float*)d_in[5];
    const float* Wf_b     = (const float*)d_in[6];
    const float* bf_b     = (const float*)d_in[7];
    const float* Ws_b     = (const float*)d_in[8];
    const float* bs_b     = (const float*)d_in[9];
    const float* Wf_out   = (const float*)d_in[10];
    const float* bf_out   = (const float*)d_in[11];
    const float* Ws_out   = (const float*)d_in[12];
    const float* bs_out   = (const float*)d_in[13];
    float* out = (float*)d_out;

    cudaFuncSetAttribute(k_gemm_mma, cudaFuncAttributeMaxDynamicSharedMemorySize,
                         SMEM_DYN_GEMM);

    // front (zero + weight prep + init+quant)
    k_front<<<PREP_BLKS + ZERO_BLKS + INIT_BLKS, 256>>>(p, W_init, b_init, Ws_b, Wf_b);
    // CSR build (proven 3-phase scan)
    k_hist<<<(NEDGES + 255) / 256, 256>>>(e_rows);
    k_scanA<<<NBLK, 256>>>();
    k_scanB<<<1, 256>>>();
    k_scanC<<<NBLK, 256>>>();
    k_scatter<<<(NEDGES + 255) / 256, 256>>>(e_rows, e_cols, adj_vals);

    // 4 graph-conv layers (two residual blocks); gemm fuses next layer's quant
    for (int L = 0; L < 4; ++L) {
        int mode = L & 1;   // 0: X->NET, 1: NET->X (+residual)
        k_spmm<<<NNODES / 8, 256>>>();
        k_gemm_mma<<<MROWS / 128, 512, SMEM_DYN_GEMM>>>(mode, L, (L < 3) ? 1 : 0,
                                                        bs_b + (size_t)L * HID,
                                                        bf_b + (size_t)L * HID);
    }

    // final 128 -> 3 (linearity: spmm(X)@W == spmm(X@W))
    k_fin_gemm<<<(MROWS * 32 + 255) / 256, 256>>>(Ws_out, bs_out, Wf_out, bf_out, out);
    k_fin_spmm<<<(NNODES + 255) / 256, 256>>>(out);
}

// round 16
// speedup vs baseline: 1.0594x; 1.0594x over previous
#include <cuda_runtime.h>
#include <cuda_bf16.h>
#include <cstdint>

#define NNODES 40000
#define NEDGES 640000
#define HID    128
#define MROWS  80000   // BATCH * NNODES
#define KPAD   40      // padded k-stride (bf16 elems) -> 80B rows, ldmatrix conflict-free
#define NBLK   157     // ceil(40000/256) scan blocks

// ---------------- device scratch (no allocations allowed) ----------------
__device__ float g_X[(size_t)MROWS * HID];
__device__ float g_NET[(size_t)MROWS * HID];
__device__ float g_AGG[(size_t)MROWS * HID];
__device__ short g_Q[(size_t)NNODES * 256];   // int16 relu(x), interleaved [node][batch][128]
__device__ float2 g_S2[NNODES];               // dequant scale {batch0, batch1}
__device__ int   g_rowptr[NNODES + 1];
__device__ int   g_cursor[NNODES];
__device__ int   g_cols[NEDGES];
__device__ float g_vals[NEDGES];
__device__ int   g_scanbuf[NBLK * 256];
__device__ int   g_bsum[NBLK];
// pre-split transposed weights: [4 layers][8 chunks][n=128][k=KPAD] bf16 hi/lo
__device__ unsigned short g_Bh16[4 * 8 * 128 * KPAD];
__device__ unsigned short g_Bl16[4 * 8 * 128 * KPAD];

// ---------------- helpers ----------------
__device__ __forceinline__ uint32_t smem_u32(const void* p) {
    uint32_t a;
    asm("{ .reg .u64 t; cvta.to.shared.u64 t, %1; cvt.u32.u64 %0, t; }" : "=r"(a) : "l"(p));
    return a;
}

__device__ __forceinline__ void split_bf16(float v, unsigned short& hi, unsigned short& lo) {
    __nv_bfloat16 h = __float2bfloat16(v);
    float r = v - __bfloat162float(h);
    __nv_bfloat16 l = __float2bfloat16(r);
    hi = __bfloat16_as_ushort(h);
    lo = __bfloat16_as_ushort(l);
}

// interleaved Q offset for logical row m (batch-major), column n
__device__ __forceinline__ size_t qoff(int m, int n) {
    return (m < NNODES) ? ((size_t)m * 256 + n)
                        : ((size_t)(m - NNODES) * 256 + 128 + n);
}

#define LDSM4(r0, r1, r2, r3, addr) \
    asm volatile("ldmatrix.sync.aligned.m8n8.x4.shared.b16 {%0,%1,%2,%3}, [%4];" \
        : "=r"(r0), "=r"(r1), "=r"(r2), "=r"(r3) : "r"(addr))

#define MMA16816(d, a, b0, b1) \
    asm volatile("mma.sync.aligned.m16n8k16.row.col.f32.bf16.bf16.f32 " \
        "{%0,%1,%2,%3}, {%4,%5,%6,%7}, {%8,%9}, {%0,%1,%2,%3};" \
        : "+f"((d)[0]), "+f"((d)[1]), "+f"((d)[2]), "+f"((d)[3]) \
        : "r"((a)[0]), "r"((a)[1]), "r"((a)[2]), "r"((a)[3]), "r"(b0), "r"(b1))

#define CP16(dst, src) \
    asm volatile("cp.async.cg.shared.global [%0], [%1], 16;" :: "r"(dst), "l"(src))
#define CP_COMMIT() asm volatile("cp.async.commit_group;" ::: "memory")
#define CP_WAIT0()  asm volatile("cp.async.wait_group 0;" ::: "memory")

// ---------------- front kernel: zero ∥ weight prep ∥ init linear (+quant) ----------------
#define PREP_BLKS 128            // 32768 threads
#define ZERO_BLKS NBLK           // 157
#define INIT_BLKS 10000          // MROWS*32/256

__global__ void k_front(const float* __restrict__ p, const float* __restrict__ Wi,
                        const float* __restrict__ bi,
                        const float* __restrict__ Ws_b, const float* __restrict__ Wf_b) {
    int b = blockIdx.x;
    int tid = threadIdx.x;
    if (b < PREP_BLKS) {
        int idx = b * 256 + tid;             // (L, c, n, kq)
        int kq = idx & 7;
        int n = (idx >> 3) & 127;
        int c = (idx >> 10) & 7;
        int L = idx >> 13;
        const float* Ws = Ws_b + (size_t)L * HID * HID;
        const float* Wf = Wf_b + (size_t)L * HID * HID;
        size_t base = ((size_t)(L * 8 + c) * 128 + n) * KPAD;
        #pragma unroll
        for (int e = 0; e < 4; ++e) {
            int k = kq * 4 + e;
            int gk = c * 32 + k;
            float v = (gk < HID) ? Ws[(size_t)gk * HID + n] : Wf[(size_t)(gk - HID) * HID + n];
            unsigned short hi, lo;
            split_bf16(v, hi, lo);
            g_Bh16[base + k] = hi;
            g_Bl16[base + k] = lo;
        }
        return;
    }
    if (b < PREP_BLKS + ZERO_BLKS) {
        int i = (b - PREP_BLKS) * 256 + tid;
        if (i < NNODES) g_cursor[i] = 0;
        return;
    }
    // init: x = p @ W_init + b_init, warp per row; fused int16 quant of relu(x)
    int idx = (b - PREP_BLKS - ZERO_BLKS) * 256 + tid;
    int m = idx >> 5;
    int lane = idx & 31;
    int h = lane * 4;
    float p0 = p[m * 3 + 0], p1 = p[m * 3 + 1], p2 = p[m * 3 + 2];
    float4 w0 = *(const float4*)&Wi[0 * HID + h];
    float4 w1 = *(const float4*)&Wi[1 * HID + h];
    float4 w2 = *(const float4*)&Wi[2 * HID + h];
    float4 bb = *(const float4*)&bi[h];
    float4 o;
    o.x = fmaf(p0, w0.x, fmaf(p1, w1.x, fmaf(p2, w2.x, bb.x)));
    o.y = fmaf(p0, w0.y, fmaf(p1, w1.y, fmaf(p2, w2.y, bb.y)));
    o.z = fmaf(p0, w0.z, fmaf(p1, w1.z, fmaf(p2, w2.z, bb.z)));
    o.w = fmaf(p0, w0.w, fmaf(p1, w1.w, fmaf(p2, w2.w, bb.w)));
    *(float4*)&g_X[(size_t)m * HID + h] = o;
    float rx = fmaxf(o.x, 0.f), ry = fmaxf(o.y, 0.f);
    float rz = fmaxf(o.z, 0.f), rw = fmaxf(o.w, 0.f);
    float mx = fmaxf(fmaxf(rx, ry), fmaxf(rz, rw));
    #pragma unroll
    for (int of = 16; of; of >>= 1)
        mx = fmaxf(mx, __shfl_xor_sync(0xffffffffu, mx, of));
    float inv = (mx > 0.f) ? 32766.f / mx : 0.f;
    short4 q;
    q.x = (short)__float2int_rn(rx * inv);
    q.y = (short)__float2int_rn(ry * inv);
    q.z = (short)__float2int_rn(rz * inv);
    q.w = (short)__float2int_rn(rw * inv);
    *(short4*)&g_Q[qoff(m, h)] = q;
    if (lane == 0) {
        float sc = (mx > 0.f) ? mx * (1.f / 32766.f) : 0.f;
        if (m < NNODES) g_S2[m].x = sc;
        else            g_S2[m - NNODES].y = sc;
    }
}

// ---------------- CSR build (proven 3-phase scan) ----------------
__global__ void k_hist(const int* __restrict__ rows) {
    int i = blockIdx.x * blockDim.x + threadIdx.x;
    if (i < NEDGES) atomicAdd(&g_cursor[rows[i]], 1);
}

__global__ void k_scanA() {
    __shared__ int ws[8];
    int tid = threadIdx.x, lane = tid & 31, wid = tid >> 5;
    int i = blockIdx.x * 256 + tid;
    int c = (i < NNODES) ? g_cursor[i] : 0;
    int v = c;
    #pragma unroll
    for (int o = 1; o < 32; o <<= 1) {
        int t = __shfl_up_sync(0xffffffffu, v, o);
        if (lane >= o) v += t;
    }
    if (lane == 31) ws[wid] = v;
    __syncthreads();
    if (wid == 0) {
        int w = (lane < 8) ? ws[lane] : 0;
        #pragma unroll
        for (int o = 1; o < 8; o <<= 1) {
            int t = __shfl_up_sync(0xffffffffu, w, o);
            if (lane >= o) w += t;
        }
        if (lane < 8) ws[lane] = w;
    }
    __syncthreads();
    int incl = v + (wid > 0 ? ws[wid - 1] : 0);
    g_scanbuf[blockIdx.x * 256 + tid] = incl;
    if (tid == 255) g_bsum[blockIdx.x] = incl;
}

__global__ void k_scanB() {
    __shared__ int ws[8];
    int tid = threadIdx.x, lane = tid & 31, wid = tid >> 5;
    int b = (tid < NBLK) ? g_bsum[tid] : 0;
    int v = b;
    #pragma unroll
    for (int o = 1; o < 32; o <<= 1) {
        int t = __shfl_up_sync(0xffffffffu, v, o);
        if (lane >= o) v += t;
    }
    if (lane == 31) ws[wid] = v;
    __syncthreads();
    if (wid == 0) {
        int w = (lane < 8) ? ws[lane] : 0;
        #pragma unroll
        for (int o = 1; o < 8; o <<= 1) {
            int t = __shfl_up_sync(0xffffffffu, w, o);
            if (lane >= o) w += t;
        }
        if (lane < 8) ws[lane] = w;
    }
    __syncthreads();
    int incl = v + (wid > 0 ? ws[wid - 1] : 0);
    if (tid < NBLK) g_bsum[tid] = incl - b;   // exclusive
}

__global__ void k_scanC() {
    int i = blockIdx.x * 256 + threadIdx.x;
    if (i < NNODES) {
        int incl = g_scanbuf[blockIdx.x * 256 + threadIdx.x] + g_bsum[blockIdx.x];
        int c = g_cursor[i];
        g_rowptr[i + 1] = incl;
        g_cursor[i] = incl - c;
        if (i == 0) g_rowptr[0] = 0;
    }
}

__global__ void k_scatter(const int* __restrict__ rows, const int* __restrict__ cols,
                          const float* __restrict__ vals) {
    int i = blockIdx.x * blockDim.x + threadIdx.x;
    if (i < NEDGES) {
        int r = rows[i];
        int pos = atomicAdd(&g_cursor[r], 1);
        g_cols[pos] = cols[i];
        g_vals[pos] = vals[i];
    }
}

// ---------------- spmm: AGG(fp32) = A * dequant(Q) ----------------
// warp = node; lanes 0-15 batch0, 16-31 batch1; one LDG.128 per lane per edge
// (the edge's full 512B [node][2][128] int16 block is contiguous).
__device__ __forceinline__ void acc8i(float* acc, int4 r, float vs) {
    acc[0] = fmaf(vs, (float)(short)(r.x), acc[0]);
    acc[1] = fmaf(vs, (float)(short)(r.x >> 16), acc[1]);
    acc[2] = fmaf(vs, (float)(short)(r.y), acc[2]);
    acc[3] = fmaf(vs, (float)(short)(r.y >> 16), acc[3]);
    acc[4] = fmaf(vs, (float)(short)(r.z), acc[4]);
    acc[5] = fmaf(vs, (float)(short)(r.z >> 16), acc[5]);
    acc[6] = fmaf(vs, (float)(short)(r.w), acc[6]);
    acc[7] = fmaf(vs, (float)(short)(r.w >> 16), acc[7]);
}

__global__ void k_spmm() {
    int w = (blockIdx.x * blockDim.x + threadIdx.x) >> 5;   // node
    int lane = threadIdx.x & 31;
    if (w >= NNODES) return;
    int s = g_rowptr[w], e = g_rowptr[w + 1];
    // lane covers shorts [lane*8, lane*8+8) of the node's 256-short block
    const short* __restrict__ qb = g_Q + lane * 8;
    int half = lane >> 4;
    float acc[8];
    #pragma unroll
    for (int k = 0; k < 8; ++k) acc[k] = 0.f;
    int j = s;
    for (; j + 2 <= e; j += 2) {
        int c0 = g_cols[j], c1 = g_cols[j + 1];
        float v0 = g_vals[j], v1 = g_vals[j + 1];
        float2 sA = g_S2[c0], sB = g_S2[c1];
        int4 r0 = *(const int4*)(qb + (size_t)c0 * 256);
        int4 r1 = *(const int4*)(qb + (size_t)c1 * 256);
        acc8i(acc, r0, v0 * (half ? sA.y : sA.x));
        acc8i(acc, r1, v1 * (half ? sB.y : sB.x));
    }
    if (j < e) {
        int c0 = g_cols[j];
        float v0 = g_vals[j];
        float2 sA = g_S2[c0];
        int4 r0 = *(const int4*)(qb + (size_t)c0 * 256);
        acc8i(acc, r0, v0 * (half ? sA.y : sA.x));
    }
    // store fp32 AGG (batch-major rows, matching GEMM consumption)
    int li = lane & 15;
    float* dst = &g_AGG[((size_t)half * NNODES + w) * HID + li * 8];
    *(float4*)dst = make_float4(acc[0], acc[1], acc[2], acc[3]);
    *(float4*)(dst + 4) = make_float4(acc[4], acc[5], acc[6], acc[7]);
}

// ---------------- mma.sync bf16 3-split GEMM, double-buffered + fused output quant ----------------
#define CHUNK_BYTES (128 * KPAD * 2)
#define BUF_BYTES   (4 * CHUNK_BYTES)
#define SMEM_DYN_GEMM (2 * BUF_BYTES)

__global__ void __launch_bounds__(512, 1) k_gemm_mma(int mode, int L, int doq,
        const float* __restrict__ bs, const float* __restrict__ bf) {
    const float* __restrict__ A1 = mode ? g_NET : g_X;
    float* __restrict__ C = mode ? g_X : g_NET;

    extern __shared__ __align__(16) char dyn_smem[];
    __shared__ float s_bias[128];
    __shared__ float s_rmax[4][128];

    const int tid = threadIdx.x;
    const int lane = tid & 31, w = tid >> 5;
    const int m0 = blockIdx.x * 128;
    const int mw = (w & 3) * 32;
    const int nw = (w >> 2) * 32;

    if (tid < 128) s_bias[tid] = bs[tid] + bf[tid];

    const uint32_t sb = smem_u32(dyn_smem);

    const int a_row = lane & 15;
    const int a_k   = (lane >> 4) * 8;
    const int b_row = ((lane >> 4) & 1) * 8 + (lane & 7);
    const int b_k   = ((lane >> 3) & 1) * 8;

    float acc[2][4][4];
    #pragma unroll
    for (int i = 0; i < 2; ++i)
        #pragma unroll
        for (int j = 0; j < 4; ++j)
            #pragma unroll
            for (int q = 0; q < 4; ++q) acc[i][j][q] = 0.f;

    const unsigned short* __restrict__ Bh = g_Bh16 + (size_t)L * 8 * 128 * KPAD;
    const unsigned short* __restrict__ Bl = g_Bl16 + (size_t)L * 8 * 128 * KPAD;

    const int row0 = tid >> 3, row1 = (tid + 512) >> 3;
    const int q0 = (tid & 7) * 4, q1 = ((tid + 512) & 7) * 4;

    {
        #pragma unroll
        for (int h = 0; h < 2; ++h) {
            int row = h ? row1 : row0;
            int q = h ? q1 : q0;
            float4 v = *(const float4*)&A1[(size_t)(m0 + row) * HID + q];
            v.x = fmaxf(v.x, 0.f); v.y = fmaxf(v.y, 0.f);
            v.z = fmaxf(v.z, 0.f); v.w = fmaxf(v.w, 0.f);
            unsigned short hh[4], ll[4];
            split_bf16(v.x, hh[0], ll[0]); split_bf16(v.y, hh[1], ll[1]);
            split_bf16(v.z, hh[2], ll[2]); split_bf16(v.w, hh[3], ll[3]);
            uint32_t eo = (uint32_t)(row * KPAD + q) * 2;
            *(uint2*)(dyn_smem + eo) = *(uint2*)hh;
            *(uint2*)(dyn_smem + CHUNK_BYTES + eo) = *(uint2*)ll;
        }
        const char* bh_src = (const char*)Bh;
        const char* bl_src = (const char*)Bl;
        for (int i = tid; i < 640; i += 512) {
            CP16(sb + 2 * CHUNK_BYTES + i * 16, bh_src + i * 16);
            CP16(sb + 3 * CHUNK_BYTES + i * 16, bl_src + i * 16);
        }
        CP_COMMIT();
        CP_WAIT0();
    }
    __syncthreads();

    int buf = 0;
    #pragma unroll 1
    for (int c = 0; c < 8; ++c) {
        float4 vn0, vn1;
        if (c < 7) {
            const float* __restrict__ asrc = (c + 1 < 4) ? A1 : (const float*)g_AGG;
            const int kbase = ((c + 1) & 3) * 32;
            vn0 = *(const float4*)&asrc[(size_t)(m0 + row0) * HID + kbase + q0];
            vn1 = *(const float4*)&asrc[(size_t)(m0 + row1) * HID + kbase + q1];
            const uint32_t nb = sb + (buf ^ 1) * BUF_BYTES;
            const char* bh_src = (const char*)(Bh + (size_t)(c + 1) * 128 * KPAD);
            const char* bl_src = (const char*)(Bl + (size_t)(c + 1) * 128 * KPAD);
            for (int i = tid; i < 640; i += 512) {
                CP16(nb + 2 * CHUNK_BYTES + i * 16, bh_src + i * 16);
                CP16(nb + 3 * CHUNK_BYTES + i * 16, bl_src + i * 16);
            }
            CP_COMMIT();
        }

        const uint32_t cb = sb + buf * BUF_BYTES;
        #pragma unroll
        for (int ks = 0; ks < 32; ks += 16) {
            uint32_t ah[2][4], al[2][4];
            #pragma unroll
            for (int mt = 0; mt < 2; ++mt) {
                uint32_t ao = (uint32_t)(((mw + mt * 16 + a_row) * KPAD + ks + a_k) * 2);
                LDSM4(ah[mt][0], ah[mt][1], ah[mt][2], ah[mt][3], cb + ao);
                LDSM4(al[mt][0], al[mt][1], al[mt][2], al[mt][3], cb + CHUNK_BYTES + ao);
            }
            #pragma unroll
            for (int nt = 0; nt < 2; ++nt) {
                uint32_t bo = (uint32_t)(((nw + nt * 16 + b_row) * KPAD + ks + b_k) * 2);
                uint32_t bh4[4], bl4[4];
                LDSM4(bh4[0], bh4[1], bh4[2], bh4[3], cb + 2 * CHUNK_BYTES + bo);
                LDSM4(bl4[0], bl4[1], bl4[2], bl4[3], cb + 3 * CHUNK_BYTES + bo);
                #pragma unroll
                for (int mt = 0; mt < 2; ++mt) {
                    #pragma unroll
                    for (int s = 0; s < 2; ++s) {
                        float* d = acc[mt][nt * 2 + s];
                        MMA16816(d, ah[mt], bh4[2 * s], bh4[2 * s + 1]);
                        MMA16816(d, ah[mt], bl4[2 * s], bl4[2 * s + 1]);
                        MMA16816(d, al[mt], bh4[2 * s], bh4[2 * s + 1]);
                    }
                }
            }
        }

        if (c < 7) {
            char* nbp = dyn_smem + (buf ^ 1) * BUF_BYTES;
            if (c + 1 < 4) {
                vn0.x = fmaxf(vn0.x, 0.f); vn0.y = fmaxf(vn0.y, 0.f);
                vn0.z = fmaxf(vn0.z, 0.f); vn0.w = fmaxf(vn0.w, 0.f);
                vn1.x = fmaxf(vn1.x, 0.f); vn1.y = fmaxf(vn1.y, 0.f);
                vn1.z = fmaxf(vn1.z, 0.f); vn1.w = fmaxf(vn1.w, 0.f);
            }
            unsigned short h0[4], l0[4], h1[4], l1[4];
            split_bf16(vn0.x, h0[0], l0[0]); split_bf16(vn0.y, h0[1], l0[1]);
            split_bf16(vn0.z, h0[2], l0[2]); split_bf16(vn0.w, h0[3], l0[3]);
            split_bf16(vn1.x, h1[0], l1[0]); split_bf16(vn1.y, h1[1], l1[1]);
            split_bf16(vn1.z, h1[2], l1[2]); split_bf16(vn1.w, h1[3], l1[3]);
            uint32_t eo0 = (uint32_t)(row0 * KPAD + q0) * 2;
            uint32_t eo1 = (uint32_t)(row1 * KPAD + q1) * 2;
            *(uint2*)(nbp + eo0) = *(uint2*)h0;
            *(uint2*)(nbp + CHUNK_BYTES + eo0) = *(uint2*)l0;
            *(uint2*)(nbp + eo1) = *(uint2*)h1;
            *(uint2*)(nbp + CHUNK_BYTES + eo1) = *(uint2*)l1;
            CP_WAIT0();
            __syncthreads();
            buf ^= 1;
        }
    }

    // ---- epilogue: bias + optional residual -> store C ----
    const int gid = lane >> 2, tig = lane & 3;
    #pragma unroll
    for (int mt = 0; mt < 2; ++mt) {
        #pragma unroll
        for (int nt = 0; nt < 4; ++nt) {
            int m = m0 + mw + mt * 16 + gid;
            int n = nw + nt * 8 + tig * 2;
            float b0 = s_bias[n], b1 = s_bias[n + 1];
            acc[mt][nt][0] += b0; acc[mt][nt][1] += b1;
            acc[mt][nt][2] += b0; acc[mt][nt][3] += b1;
            if (mode) {
                float2 r0 = *(const float2*)&C[(size_t)m * HID + n];
                float2 r1 = *(const float2*)&C[(size_t)(m + 8) * HID + n];
                acc[mt][nt][0] += r0.x; acc[mt][nt][1] += r0.y;
                acc[mt][nt][2] += r1.x; acc[mt][nt][3] += r1.y;
            }
            *(float2*)&C[(size_t)m * HID + n] = make_float2(acc[mt][nt][0], acc[mt][nt][1]);
            *(float2*)&C[(size_t)(m + 8) * HID + n] = make_float2(acc[mt][nt][2], acc[mt][nt][3]);
        }
    }

    // ---- fused quantization of relu(C) for next layer's spmm (interleaved layout) ----
    if (doq) {
        float rmax[2][2];
        #pragma unroll
        for (int mt = 0; mt < 2; ++mt) {
            float mA = 0.f, mB = 0.f;
            #pragma unroll
            for (int nt = 0; nt < 4; ++nt) {
                mA = fmaxf(mA, fmaxf(acc[mt][nt][0], acc[mt][nt][1]));
                mB = fmaxf(mB, fmaxf(acc[mt][nt][2], acc[mt][nt][3]));
            }
            rmax[mt][0] = mA; rmax[mt][1] = mB;
        }
        #pragma unroll
        for (int mt = 0; mt < 2; ++mt)
            #pragma unroll
            for (int hf = 0; hf < 2; ++hf) {
                float v = rmax[mt][hf];
                v = fmaxf(v, __shfl_xor_sync(0xffffffffu, v, 1));
                v = fmaxf(v, __shfl_xor_sync(0xffffffffu, v, 2));
                rmax[mt][hf] = v;
            }
        const int wg = w >> 2;
        if (tig == 0) {
            #pragma unroll
            for (int mt = 0; mt < 2; ++mt)
                #pragma unroll
                for (int hf = 0; hf < 2; ++hf)
                    s_rmax[wg][mw + mt * 16 + hf * 8 + gid] = rmax[mt][hf];
        }
        __syncthreads();
        #pragma unroll
        for (int mt = 0; mt < 2; ++mt) {
            #pragma unroll
            for (int hf = 0; hf < 2; ++hf) {
                int row = mw + mt * 16 + hf * 8 + gid;
                float rm = fmaxf(fmaxf(s_rmax[0][row], s_rmax[1][row]),
                                 fmaxf(s_rmax[2][row], s_rmax[3][row]));
                float inv = (rm > 0.f) ? 32766.f / rm : 0.f;
                int m = m0 + row;
                #pragma unroll
                for (int nt = 0; nt < 4; ++nt) {
                    int n = nw + nt * 8 + tig * 2;
                    short2 qq;
                    qq.x = (short)__float2int_rn(fmaxf(acc[mt][nt][hf * 2 + 0], 0.f) * inv);
                    qq.y = (short)__float2int_rn(fmaxf(acc[mt][nt][hf * 2 + 1], 0.f) * inv);
                    *(short2*)&g_Q[qoff(m, n)] = qq;
                }
                if (wg == 0 && tig == 0) {
                    float sc = (rm > 0.f) ? rm * (1.f / 32766.f) : 0.f;
                    if (m < NNODES) g_S2[m].x = sc;
                    else            g_S2[m - NNODES].y = sc;
                }
            }
        }
    }
}

// ---------------- final layer: Ys/Yf = relu(x) @ [Ws_out|Wf_out] ----------------
__global__ void k_fin_gemm(const float* __restrict__ Wso, const float* __restrict__ bso,
                           const float* __restrict__ Wfo, const float* __restrict__ bfo,
                           float* __restrict__ out) {
    int w = (blockIdx.x * blockDim.x + threadIdx.x) >> 5;
    int lane = threadIdx.x & 31;
    if (w >= MROWS) return;
    int k0 = lane * 4;
    float4 x = *(const float4*)&g_X[(size_t)w * HID + k0];
    float xv[4] = { fmaxf(x.x, 0.f), fmaxf(x.y, 0.f), fmaxf(x.z, 0.f), fmaxf(x.w, 0.f) };
    float s[6] = {0.f, 0.f, 0.f, 0.f, 0.f, 0.f};
    #pragma unroll
    for (int i = 0; i < 4; ++i) {
        int k = k0 + i;
        s[0] = fmaf(xv[i], Wso[k * 3 + 0], s[0]);
        s[1] = fmaf(xv[i], Wso[k * 3 + 1], s[1]);
        s[2] = fmaf(xv[i], Wso[k * 3 + 2], s[2]);
        s[3] = fmaf(xv[i], Wfo[k * 3 + 0], s[3]);
        s[4] = fmaf(xv[i], Wfo[k * 3 + 1], s[4]);
        s[5] = fmaf(xv[i], Wfo[k * 3 + 2], s[5]);
    }
    #pragma unroll
    for (int o = 16; o; o >>= 1) {
        #pragma unroll
        for (int c = 0; c < 6; ++c)
            s[c] += __shfl_down_sync(0xffffffffu, s[c], o);
    }
    if (lane == 0) {
        out[(size_t)w * 3 + 0] = s[0] + bso[0] + bfo[0];
        out[(size_t)w * 3 + 1] = s[1] + bso[1] + bfo[1];
        out[(size_t)w * 3 + 2] = s[2] + bso[2] + bfo[2];
        g_AGG[(size_t)w * 3 + 0] = s[3];
        g_AGG[(size_t)w * 3 + 1] = s[4];
        g_AGG[(size_t)w * 3 + 2] = s[5];
    }
}

__global__ void k_fin_spmm(float* __restrict__ out) {
    int n = blockIdx.x * blockDim.x + threadIdx.x;
    if (n >= NNODES) return;
    int s = g_rowptr[n], e = g_rowptr[n + 1];
    float a[6] = {0.f, 0.f, 0.f, 0.f, 0.f, 0.f};
    for (int j = s; j < e; ++j) {
        int c = g_cols[j];
        float v = g_vals[j];
        const float* y0 = &g_AGG[(size_t)c * 3];
        const float* y1 = &g_AGG[((size_t)NNODES + c) * 3];
        a[0] = fmaf(v, y0[0], a[0]);
        a[1] = fmaf(v, y0[1], a[1]);
        a[2] = fmaf(v, y0[2], a[2]);
        a[3] = fmaf(v, y1[0], a[3]);
        a[4] = fmaf(v, y1[1], a[4]);
        a[5] = fmaf(v, y1[2], a[5]);
    }
    float* o0 = &out[(size_t)n * 3];
    float* o1 = &out[((size_t)NNODES + n) * 3];
    o0[0] += a[0]; o0[1] += a[1]; o0[2] += a[2];
    o1[0] += a[3]; o1[1] += a[4]; o1[2] += a[5];
}

// ---------------- launch ----------------
extern "C" void kernel_launch(void* const* d_in, const int* in_sizes, int n_in,
                              void* d_out, int out_size) {
    const float* p        = (const float*)d_in[0];
    const float* adj_vals = (const float*)d_in[1];
    const int*   e_rows   = (const int*)d_in[2];
    const int*   e_cols   = (const int*)d_in[3];
    const float* W_init   = (const float*)d_in[4];
    const float* b_init   = (const float*)d_in[5];
    const float* Wf_b     = (const float*)d_in[6];
    const float* bf_b     = (const float*)d_in[7];
    const float* Ws_b     = (const float*)d_in[8];
    const float* bs_b     = (const float*)d_in[9];
    const float* Wf_out   = (const float*)d_in[10];
    const float* bf_out   = (const float*)d_in[11];
    const float* Ws_out   = (const float*)d_in[12];
    const float* bs_out   = (const float*)d_in[13];
    float* out = (float*)d_out;

    cudaFuncSetAttribute(k_gemm_mma, cudaFuncAttributeMaxDynamicSharedMemorySize,
                         SMEM_DYN_GEMM);

    // front (zero + weight prep + init+quant)
    k_front<<<PREP_BLKS + ZERO_BLKS + INIT_BLKS, 256>>>(p, W_init, b_init, Ws_b, Wf_b);
    // CSR build (proven 3-phase scan)
    k_hist<<<(NEDGES + 255) / 256, 256>>>(e_rows);
    k_scanA<<<NBLK, 256>>>();
    k_scanB<<<1, 256>>>();
    k_scanC<<<NBLK, 256>>>();
    k_scatter<<<(NEDGES + 255) / 256, 256>>>(e_rows, e_cols, adj_vals);

    // 4 graph-conv layers (two residual blocks); gemm fuses next layer's quant
    for (int L = 0; L < 4; ++L) {
        int mode = L & 1;   // 0: X->NET, 1: NET->X (+residual)
        k_spmm<<<NNODES / 8, 256>>>();
        k_gemm_mma<<<MROWS / 128, 512, SMEM_DYN_GEMM>>>(mode, L, (L < 3) ? 1 : 0,
                                                        bs_b + (size_t)L * HID,
                                                        bf_b + (size_t)L * HID);
    }

    // final 128 -> 3 (linearity: spmm(X)@W == spmm(X@W))
    k_fin_gemm<<<(MROWS * 32 + 255) / 256, 256>>>(Ws_out, bs_out, Wf_out, bf_out, out);
    k_fin_spmm<<<(NNODES + 255) / 256, 256>>>(out);
}